// round 4
// baseline (speedup 1.0000x reference)
#include <cuda_runtime.h>
#include <math.h>

// NoisyTopKRouter eval-mode:
//   inputs:  x [4,8192,2048] f32, W_gate [2048,8] f32, W_noise (UNUSED in eval), top_k=2
//   outputs (concatenated f32 in d_out):
//     dispatch_weights [4,8192,2]  (65536)
//     top_k_idx        [4,8192,2]  (65536, cast to float)
//     auxiliary_loss   scalar      (1)

#define D        2048
#define D4       512        // D / 4
#define NEXP     8
#define RPW      8          // rows per warp
#define WPB      8          // warps per block
#define RPB      (RPW*WPB)  // rows per block = 64

__device__ float g_load[NEXP];
__device__ float g_imp[NEXP];

__device__ __forceinline__ unsigned long long pack2(float x, float y) {
    unsigned long long r;
    asm("mov.b64 %0, {%1, %2};" : "=l"(r) : "f"(x), "f"(y));
    return r;
}
__device__ __forceinline__ void unpack2(unsigned long long v, float& x, float& y) {
    asm("mov.b64 {%0, %1}, %2;" : "=f"(x), "=f"(y) : "l"(v));
}
__device__ __forceinline__ void ffma2(unsigned long long& d,
                                      unsigned long long a, unsigned long long b) {
    asm("fma.rn.f32x2 %0, %1, %2, %0;" : "+l"(d) : "l"(a), "l"(b));
}
__device__ __forceinline__ unsigned long long add2(unsigned long long a,
                                                   unsigned long long b) {
    unsigned long long r;
    asm("add.rn.f32x2 %0, %1, %2;" : "=l"(r) : "l"(a), "l"(b));
    return r;
}

__global__ void zero_kernel() {
    int t = threadIdx.x;
    if (t < NEXP) { g_load[t] = 0.f; g_imp[t] = 0.f; }
}

__global__ __launch_bounds__(256, 2)
void router_main(const float* __restrict__ x, const float* __restrict__ Wg,
                 float* __restrict__ out_w, float* __restrict__ out_idx) {
    __shared__ float s_load[NEXP];
    __shared__ float s_imp[NEXP];
    const int tid  = threadIdx.x;
    const int warp = tid >> 5;
    const int lane = tid & 31;

    if (tid < NEXP) { s_load[tid] = 0.f; s_imp[tid] = 0.f; }
    __syncthreads();

    const int r0 = (blockIdx.x * WPB + warp) * RPW;     // first row for this warp

    const float4*     x4 = (const float4*)x;
    const ulonglong2* wq = (const ulonglong2*)Wg;        // W_gate as f32x2 pairs

    // acc[rr][p] : f32x2 accumulator for experts (2p, 2p+1) of row r0+rr
    unsigned long long acc[RPW][4];
#pragma unroll
    for (int rr = 0; rr < RPW; rr++)
#pragma unroll
        for (int p = 0; p < 4; p++) acc[rr][p] = 0ull;

#pragma unroll 1
    for (int i = 0; i < 16; i++) {                       // 16 column groups of 128
        float4 xv[RPW];
#pragma unroll
        for (int rr = 0; rr < RPW; rr++)
            xv[rr] = __ldcs(&x4[(r0 + rr) * D4 + i * 32 + lane]);  // streaming

        const int cbase = i * 128 + lane * 4;            // this lane's 4 columns
#pragma unroll
        for (int j = 0; j < 4; j++) {
            const int c = cbase + j;
            ulonglong2 wa = __ldg(&wq[c * 2]);           // experts 0..3 (L1-resident)
            ulonglong2 wb = __ldg(&wq[c * 2 + 1]);       // experts 4..7
#pragma unroll
            for (int rr = 0; rr < RPW; rr++) {
                float xc = (j == 0) ? xv[rr].x : (j == 1) ? xv[rr].y
                         : (j == 2) ? xv[rr].z : xv[rr].w;
                unsigned long long xb = pack2(xc, xc);
                ffma2(acc[rr][0], xb, wa.x);
                ffma2(acc[rr][1], xb, wa.y);
                ffma2(acc[rr][2], xb, wb.x);
                ffma2(acc[rr][3], xb, wb.y);
            }
        }
    }

    // Cross-lane reduction: 64-bit butterfly, all lanes end with the full h-vector.
#pragma unroll
    for (int rr = 0; rr < RPW; rr++)
#pragma unroll
        for (int p = 0; p < 4; p++) {
#pragma unroll
            for (int off = 16; off > 0; off >>= 1)
                acc[rr][p] = add2(acc[rr][p],
                                  __shfl_xor_sync(0xffffffffu, acc[rr][p], off));
        }

    // Lane rr takes ownership of row r0+rr (lanes 0..7 active for the epilogue).
    unsigned long long mine[4];
#pragma unroll
    for (int rr = 0; rr < RPW; rr++)
        if (lane == rr) {
            mine[0] = acc[rr][0]; mine[1] = acc[rr][1];
            mine[2] = acc[rr][2]; mine[3] = acc[rr][3];
        }

    if (lane < RPW) {
        float h[NEXP];
        unpack2(mine[0], h[0], h[1]);
        unpack2(mine[1], h[2], h[3]);
        unpack2(mine[2], h[4], h[5]);
        unpack2(mine[3], h[6], h[7]);

        const int row = r0 + lane;

        // top-2 with jax tie-breaking (lowest index wins on equality)
        int e0 = 0; float v0 = h[0];
#pragma unroll
        for (int e = 1; e < NEXP; e++)
            if (h[e] > v0) { v0 = h[e]; e0 = e; }
        int e1 = -1; float v1 = -3.4e38f;
#pragma unroll
        for (int e = 0; e < NEXP; e++)
            if (e != e0 && h[e] > v1) { v1 = h[e]; e1 = e; }

        // softmax over [v0, v1] (v0 >= v1)
        float w0 = 1.f / (1.f + expf(v1 - v0));
        float w1 = 1.f - w0;

        // full softmax for importance
        float p[NEXP]; float Z = 0.f;
#pragma unroll
        for (int e = 0; e < NEXP; e++) { p[e] = expf(h[e] - v0); Z += p[e]; }
        float invZ = 1.f / Z;
#pragma unroll
        for (int e = 0; e < NEXP; e++) atomicAdd(&s_imp[e], p[e] * invZ);
        atomicAdd(&s_load[e0], 1.f);
        atomicAdd(&s_load[e1], 1.f);

        out_w[row * 2]       = w0;
        out_w[row * 2 + 1]   = w1;
        out_idx[row * 2]     = (float)e0;
        out_idx[row * 2 + 1] = (float)e1;
    }

    __syncthreads();
    if (tid < NEXP) {
        atomicAdd(&g_load[tid], s_load[tid]);
        atomicAdd(&g_imp[tid],  s_imp[tid]);
    }
}

__global__ void aux_kernel(float* __restrict__ out_aux) {
    if (threadIdx.x == 0 && blockIdx.x == 0) {
        float ml = 0.f, mi = 0.f;
#pragma unroll
        for (int e = 0; e < NEXP; e++) { ml += g_load[e]; mi += g_imp[e]; }
        ml *= (1.f / NEXP);
        mi *= (1.f / NEXP);
        float vl = 0.f, vi = 0.f;
#pragma unroll
        for (int e = 0; e < NEXP; e++) {
            float dl = g_load[e] - ml; vl += dl * dl;
            float di = g_imp[e]  - mi; vi += di * di;
        }
        vl *= (1.f / (NEXP - 1));   // ddof = 1
        vi *= (1.f / (NEXP - 1));
        float cv = sqrtf(vl) / (ml + 1e-6f) + sqrtf(vi) / (mi + 1e-6f);
        *out_aux = cv * 0.01f;
    }
}

extern "C" void kernel_launch(void* const* d_in, const int* in_sizes, int n_in,
                              void* d_out, int out_size) {
    const float* x  = (const float*)d_in[0];   // [4,8192,2048]
    const float* Wg = (const float*)d_in[1];   // [2048,8]
    // d_in[2] = W_noise (unused in eval mode), d_in[3] = top_k (=2)

    const int N = in_sizes[0] / D;             // 32768 rows

    float* out     = (float*)d_out;
    float* out_w   = out;                      // [N,2]
    float* out_idx = out + (size_t)N * 2;      // [N,2] indices as float
    float* out_aux = out + (size_t)N * 4;      // scalar

    zero_kernel<<<1, 32>>>();
    router_main<<<N / RPB, 256>>>(x, Wg, out_w, out_idx);
    aux_kernel<<<1, 32>>>(out_aux);
}

// round 5
// speedup vs baseline: 1.4766x; 1.4766x over previous
#include <cuda_runtime.h>
#include <math.h>

// NoisyTopKRouter eval-mode:
//   inputs:  x [4,8192,2048] f32, W_gate [2048,8] f32, W_noise (UNUSED), top_k=2
//   outputs (f32, concatenated in d_out):
//     dispatch_weights [N,2], top_k_idx [N,2] (as float), auxiliary_loss scalar

#define D        2048
#define D4       512        // D / 4
#define NEXP     8
#define RPW      8          // rows per warp
#define WPB      8          // warps per block
#define RPB      (RPW*WPB)  // rows per block = 64

__device__ float    g_load[NEXP];
__device__ float    g_imp[NEXP];
__device__ unsigned g_ctr;
// Rearranged W_gate: [(i*4+j)*2 + half][lane] 16B units, i=0..15, j=0..3, half=0..1
// half 0 = experts 0..3, half 1 = experts 4..7, for column c = i*128 + lane*4 + j.
__device__ float4   g_Wre[16 * 4 * 2 * 32];   // 64 KB

__device__ __forceinline__ unsigned long long pack2(float x, float y) {
    unsigned long long r;
    asm("mov.b64 %0, {%1, %2};" : "=l"(r) : "f"(x), "f"(y));
    return r;
}
__device__ __forceinline__ void unpack2(unsigned long long v, float& x, float& y) {
    asm("mov.b64 {%0, %1}, %2;" : "=f"(x), "=f"(y) : "l"(v));
}
__device__ __forceinline__ void ffma2(unsigned long long& d,
                                      unsigned long long a, unsigned long long b) {
    asm("fma.rn.f32x2 %0, %1, %2, %0;" : "+l"(d) : "l"(a), "l"(b));
}
__device__ __forceinline__ unsigned long long add2(unsigned long long a,
                                                   unsigned long long b) {
    unsigned long long r;
    asm("add.rn.f32x2 %0, %1, %2;" : "=l"(r) : "l"(a), "l"(b));
    return r;
}

// Rearrange W_gate into loop-order layout + zero the global accumulators.
__global__ void prep_kernel(const float* __restrict__ Wg) {
    const int c = blockIdx.x * 128 + threadIdx.x;           // column 0..2047
    const float4* Wg4 = (const float4*)Wg;
    float4 f0 = Wg4[c * 2];                                  // experts 0..3
    float4 f1 = Wg4[c * 2 + 1];                              // experts 4..7
    const int i = c >> 7, r = c & 127, lane = r >> 2, j = r & 3;
    const int base = ((i * 4 + j) * 2) * 32 + lane;
    g_Wre[base]      = f0;
    g_Wre[base + 32] = f1;
    if (blockIdx.x == 0) {
        if (threadIdx.x < NEXP) { g_load[threadIdx.x] = 0.f; g_imp[threadIdx.x] = 0.f; }
        if (threadIdx.x == NEXP) g_ctr = 0u;
    }
}

__global__ __launch_bounds__(256, 2)
void router_main(const float* __restrict__ x,
                 float* __restrict__ out_w, float* __restrict__ out_idx,
                 float* __restrict__ out_aux) {
    __shared__ float s_load[NEXP];
    __shared__ float s_imp[NEXP];
    __shared__ unsigned s_ticket;
    const int tid  = threadIdx.x;
    const int warp = tid >> 5;
    const int lane = tid & 31;

    if (tid < NEXP) { s_load[tid] = 0.f; s_imp[tid] = 0.f; }
    __syncthreads();

    const int r0 = (blockIdx.x * WPB + warp) * RPW;          // first row for this warp

    const float4*     x4 = (const float4*)x;
    const ulonglong2* wq = (const ulonglong2*)g_Wre;         // 16B units, dense per warp

    unsigned long long acc[RPW][4];
#pragma unroll
    for (int rr = 0; rr < RPW; rr++)
#pragma unroll
        for (int p = 0; p < 4; p++) acc[rr][p] = 0ull;

    const float4* xp = x4 + (size_t)r0 * D4 + lane;

#pragma unroll 1
    for (int i = 0; i < 16; i++) {                           // 16 groups of 128 cols
        float4 xv[RPW];
#pragma unroll
        for (int rr = 0; rr < RPW; rr++)
            xv[rr] = __ldcs(xp + rr * D4 + i * 32);          // streaming, dense

#pragma unroll
        for (int j = 0; j < 4; j++) {
            // Dense, L1-resident weight loads (lane stride = 16B)
            ulonglong2 wa = wq[((i * 4 + j) * 2 + 0) * 32 + lane];  // experts 0..3
            ulonglong2 wb = wq[((i * 4 + j) * 2 + 1) * 32 + lane];  // experts 4..7
#pragma unroll
            for (int rr = 0; rr < RPW; rr++) {
                float xc = (j == 0) ? xv[rr].x : (j == 1) ? xv[rr].y
                         : (j == 2) ? xv[rr].z : xv[rr].w;
                unsigned long long xb = pack2(xc, xc);
                ffma2(acc[rr][0], xb, wa.x);
                ffma2(acc[rr][1], xb, wa.y);
                ffma2(acc[rr][2], xb, wb.x);
                ffma2(acc[rr][3], xb, wb.y);
            }
        }
    }

    // Cross-lane reduction: 64-bit butterfly (once per 8 rows).
#pragma unroll
    for (int rr = 0; rr < RPW; rr++)
#pragma unroll
        for (int p = 0; p < 4; p++) {
#pragma unroll
            for (int off = 16; off > 0; off >>= 1)
                acc[rr][p] = add2(acc[rr][p],
                                  __shfl_xor_sync(0xffffffffu, acc[rr][p], off));
        }

    // Lane rr owns row r0+rr for the epilogue.
    unsigned long long mine[4];
#pragma unroll
    for (int rr = 0; rr < RPW; rr++)
        if (lane == rr) {
            mine[0] = acc[rr][0]; mine[1] = acc[rr][1];
            mine[2] = acc[rr][2]; mine[3] = acc[rr][3];
        }

    if (lane < RPW) {
        float h[NEXP];
        unpack2(mine[0], h[0], h[1]);
        unpack2(mine[1], h[2], h[3]);
        unpack2(mine[2], h[4], h[5]);
        unpack2(mine[3], h[6], h[7]);

        const int row = r0 + lane;

        // top-2 (lowest index wins ties, matching jax.lax.top_k)
        int e0 = 0; float v0 = h[0];
#pragma unroll
        for (int e = 1; e < NEXP; e++)
            if (h[e] > v0) { v0 = h[e]; e0 = e; }
        int e1 = -1; float v1 = -3.4e38f;
#pragma unroll
        for (int e = 0; e < NEXP; e++)
            if (e != e0 && h[e] > v1) { v1 = h[e]; e1 = e; }

        float w0 = 1.f / (1.f + expf(v1 - v0));
        float w1 = 1.f - w0;

        float p[NEXP]; float Z = 0.f;
#pragma unroll
        for (int e = 0; e < NEXP; e++) { p[e] = expf(h[e] - v0); Z += p[e]; }
        float invZ = 1.f / Z;
#pragma unroll
        for (int e = 0; e < NEXP; e++) atomicAdd(&s_imp[e], p[e] * invZ);
        atomicAdd(&s_load[e0], 1.f);
        atomicAdd(&s_load[e1], 1.f);

        out_w[row * 2]       = w0;
        out_w[row * 2 + 1]   = w1;
        out_idx[row * 2]     = (float)e0;
        out_idx[row * 2 + 1] = (float)e1;
    }

    __syncthreads();
    if (tid < NEXP) {
        atomicAdd(&g_load[tid], s_load[tid]);
        atomicAdd(&g_imp[tid],  s_imp[tid]);
        __threadfence();
    }
    __syncthreads();
    if (tid == 0) s_ticket = atomicAdd(&g_ctr, 1u);
    __syncthreads();

    // Last block computes the auxiliary loss (all other blocks' atomics are
    // ordered before their ticket increments via threadfence + bar).
    if (s_ticket == gridDim.x - 1 && tid == 0) {
        volatile float* vl_ = g_load;
        volatile float* vi_ = g_imp;
        float l[NEXP], im[NEXP];
        float ml = 0.f, mi = 0.f;
#pragma unroll
        for (int e = 0; e < NEXP; e++) {
            l[e] = vl_[e]; im[e] = vi_[e];
            ml += l[e];    mi += im[e];
        }
        ml *= (1.f / NEXP);
        mi *= (1.f / NEXP);
        float vl = 0.f, vi = 0.f;
#pragma unroll
        for (int e = 0; e < NEXP; e++) {
            float dl = l[e]  - ml; vl += dl * dl;
            float di = im[e] - mi; vi += di * di;
        }
        vl *= (1.f / (NEXP - 1));   // ddof = 1
        vi *= (1.f / (NEXP - 1));
        float cv = sqrtf(vl) / (ml + 1e-6f) + sqrtf(vi) / (mi + 1e-6f);
        *out_aux = cv * 0.01f;
    }
}

extern "C" void kernel_launch(void* const* d_in, const int* in_sizes, int n_in,
                              void* d_out, int out_size) {
    const float* x  = (const float*)d_in[0];   // [4,8192,2048]
    const float* Wg = (const float*)d_in[1];   // [2048,8]
    // d_in[2] = W_noise (unused in eval), d_in[3] = top_k (=2)

    const int N = in_sizes[0] / D;             // 32768 rows

    float* out     = (float*)d_out;
    float* out_w   = out;                      // [N,2]
    float* out_idx = out + (size_t)N * 2;      // [N,2]
    float* out_aux = out + (size_t)N * 4;      // scalar

    prep_kernel<<<16, 128>>>(Wg);
    router_main<<<N / RPB, 256>>>(x, out_w, out_idx, out_aux);
}

// round 6
// speedup vs baseline: 1.4882x; 1.0079x over previous
#include <cuda_runtime.h>
#include <math.h>

// NoisyTopKRouter eval-mode:
//   inputs:  x [4,8192,2048] f32, W_gate [2048,8] f32, W_noise (UNUSED), top_k=2
//   outputs (f32, concatenated in d_out):
//     dispatch_weights [N,2], top_k_idx [N,2] (as float), auxiliary_loss scalar

#define D        2048
#define D4       512        // D / 4
#define NEXP     8
#define RPW      4          // rows per warp
#define WPB      4          // warps per block (128 threads)
#define RPB      (RPW*WPB)  // rows per block = 16

__device__ float    g_load[NEXP];
__device__ float    g_imp[NEXP];
__device__ unsigned g_ctr;
// Rearranged W_gate: [(i*4+j)*2 + half][lane] 16B units, i=0..15, j=0..3, half=0..1
// half 0 = experts 0..3, half 1 = experts 4..7, for column c = i*128 + lane*4 + j.
__device__ float4   g_Wre[16 * 4 * 2 * 32];   // 64 KB

__device__ __forceinline__ unsigned long long pack2(float x, float y) {
    unsigned long long r;
    asm("mov.b64 %0, {%1, %2};" : "=l"(r) : "f"(x), "f"(y));
    return r;
}
__device__ __forceinline__ void unpack2(unsigned long long v, float& x, float& y) {
    asm("mov.b64 {%0, %1}, %2;" : "=f"(x), "=f"(y) : "l"(v));
}
__device__ __forceinline__ void ffma2(unsigned long long& d,
                                      unsigned long long a, unsigned long long b) {
    asm("fma.rn.f32x2 %0, %1, %2, %0;" : "+l"(d) : "l"(a), "l"(b));
}
__device__ __forceinline__ unsigned long long add2(unsigned long long a,
                                                   unsigned long long b) {
    unsigned long long r;
    asm("add.rn.f32x2 %0, %1, %2;" : "=l"(r) : "l"(a), "l"(b));
    return r;
}

// Rearrange W_gate into loop-order layout + zero the global accumulators.
__global__ void prep_kernel(const float* __restrict__ Wg) {
    const int c = blockIdx.x * 128 + threadIdx.x;           // column 0..2047
    const float4* Wg4 = (const float4*)Wg;
    float4 f0 = Wg4[c * 2];                                  // experts 0..3
    float4 f1 = Wg4[c * 2 + 1];                              // experts 4..7
    const int i = c >> 7, r = c & 127, lane = r >> 2, j = r & 3;
    const int base = ((i * 4 + j) * 2) * 32 + lane;
    g_Wre[base]      = f0;
    g_Wre[base + 32] = f1;
    if (blockIdx.x == 0) {
        if (threadIdx.x < NEXP) { g_load[threadIdx.x] = 0.f; g_imp[threadIdx.x] = 0.f; }
        if (threadIdx.x == NEXP) g_ctr = 0u;
    }
}

__global__ __launch_bounds__(128, 5)
void router_main(const float* __restrict__ x,
                 float* __restrict__ out_w, float* __restrict__ out_idx,
                 float* __restrict__ out_aux) {
    __shared__ float s_load[NEXP];
    __shared__ float s_imp[NEXP];
    __shared__ unsigned s_ticket;
    const int tid  = threadIdx.x;
    const int warp = tid >> 5;
    const int lane = tid & 31;

    if (tid < NEXP) { s_load[tid] = 0.f; s_imp[tid] = 0.f; }
    __syncthreads();

    const int r0 = (blockIdx.x * WPB + warp) * RPW;          // first row for this warp

    const float4*     x4 = (const float4*)x;
    const ulonglong2* wq = (const ulonglong2*)g_Wre;         // 16B units, dense per warp

    unsigned long long acc[RPW][4];
#pragma unroll
    for (int rr = 0; rr < RPW; rr++)
#pragma unroll
        for (int p = 0; p < 4; p++) acc[rr][p] = 0ull;

    const float4* xp = x4 + (size_t)r0 * D4 + lane;

    // Prime the pipeline: loads for i = 0.
    float4 xv[RPW];
#pragma unroll
    for (int rr = 0; rr < RPW; rr++)
        xv[rr] = __ldcs(xp + rr * D4);

#pragma unroll 1
    for (int i = 0; i < 16; i++) {                           // 16 groups of 128 cols
        // Prefetch next iteration's x before the FFMA chain (keeps 512B in flight).
        float4 xn[RPW];
        if (i < 15) {
#pragma unroll
            for (int rr = 0; rr < RPW; rr++)
                xn[rr] = __ldcs(xp + rr * D4 + (i + 1) * 32);
        }

#pragma unroll
        for (int j = 0; j < 4; j++) {
            // Dense, L1-resident weight loads (lane stride = 16B)
            ulonglong2 wa = wq[((i * 4 + j) * 2 + 0) * 32 + lane];  // experts 0..3
            ulonglong2 wb = wq[((i * 4 + j) * 2 + 1) * 32 + lane];  // experts 4..7
#pragma unroll
            for (int rr = 0; rr < RPW; rr++) {
                float xc = (j == 0) ? xv[rr].x : (j == 1) ? xv[rr].y
                         : (j == 2) ? xv[rr].z : xv[rr].w;
                unsigned long long xb = pack2(xc, xc);
                ffma2(acc[rr][0], xb, wa.x);
                ffma2(acc[rr][1], xb, wa.y);
                ffma2(acc[rr][2], xb, wb.x);
                ffma2(acc[rr][3], xb, wb.y);
            }
        }

#pragma unroll
        for (int rr = 0; rr < RPW; rr++) xv[rr] = xn[rr];
    }

    // Cross-lane reduction: 64-bit butterfly (once per 4 rows).
#pragma unroll
    for (int rr = 0; rr < RPW; rr++)
#pragma unroll
        for (int p = 0; p < 4; p++) {
#pragma unroll
            for (int off = 16; off > 0; off >>= 1)
                acc[rr][p] = add2(acc[rr][p],
                                  __shfl_xor_sync(0xffffffffu, acc[rr][p], off));
        }

    // Lane rr owns row r0+rr for the epilogue.
    unsigned long long mine[4];
#pragma unroll
    for (int rr = 0; rr < RPW; rr++)
        if (lane == rr) {
            mine[0] = acc[rr][0]; mine[1] = acc[rr][1];
            mine[2] = acc[rr][2]; mine[3] = acc[rr][3];
        }

    if (lane < RPW) {
        float h[NEXP];
        unpack2(mine[0], h[0], h[1]);
        unpack2(mine[1], h[2], h[3]);
        unpack2(mine[2], h[4], h[5]);
        unpack2(mine[3], h[6], h[7]);

        const int row = r0 + lane;

        // top-2 (lowest index wins ties, matching jax.lax.top_k)
        int e0 = 0; float v0 = h[0];
#pragma unroll
        for (int e = 1; e < NEXP; e++)
            if (h[e] > v0) { v0 = h[e]; e0 = e; }
        int e1 = -1; float v1 = -3.4e38f;
#pragma unroll
        for (int e = 0; e < NEXP; e++)
            if (e != e0 && h[e] > v1) { v1 = h[e]; e1 = e; }

        float w0 = 1.f / (1.f + expf(v1 - v0));
        float w1 = 1.f - w0;

        float p[NEXP]; float Z = 0.f;
#pragma unroll
        for (int e = 0; e < NEXP; e++) { p[e] = expf(h[e] - v0); Z += p[e]; }
        float invZ = 1.f / Z;
#pragma unroll
        for (int e = 0; e < NEXP; e++) atomicAdd(&s_imp[e], p[e] * invZ);
        atomicAdd(&s_load[e0], 1.f);
        atomicAdd(&s_load[e1], 1.f);

        out_w[row * 2]       = w0;
        out_w[row * 2 + 1]   = w1;
        out_idx[row * 2]     = (float)e0;
        out_idx[row * 2 + 1] = (float)e1;
    }

    __syncthreads();
    if (tid < NEXP) {
        atomicAdd(&g_load[tid], s_load[tid]);
        atomicAdd(&g_imp[tid],  s_imp[tid]);
        __threadfence();
    }
    __syncthreads();
    if (tid == 0) s_ticket = atomicAdd(&g_ctr, 1u);
    __syncthreads();

    // Last block computes the auxiliary loss.
    if (s_ticket == gridDim.x - 1 && tid == 0) {
        volatile float* vl_ = g_load;
        volatile float* vi_ = g_imp;
        float l[NEXP], im[NEXP];
        float ml = 0.f, mi = 0.f;
#pragma unroll
        for (int e = 0; e < NEXP; e++) {
            l[e] = vl_[e]; im[e] = vi_[e];
            ml += l[e];    mi += im[e];
        }
        ml *= (1.f / NEXP);
        mi *= (1.f / NEXP);
        float vl = 0.f, vi = 0.f;
#pragma unroll
        for (int e = 0; e < NEXP; e++) {
            float dl = l[e]  - ml; vl += dl * dl;
            float di = im[e] - mi; vi += di * di;
        }
        vl *= (1.f / (NEXP - 1));   // ddof = 1
        vi *= (1.f / (NEXP - 1));
        float cv = sqrtf(vl) / (ml + 1e-6f) + sqrtf(vi) / (mi + 1e-6f);
        *out_aux = cv * 0.01f;
    }
}

extern "C" void kernel_launch(void* const* d_in, const int* in_sizes, int n_in,
                              void* d_out, int out_size) {
    const float* x  = (const float*)d_in[0];   // [4,8192,2048]
    const float* Wg = (const float*)d_in[1];   // [2048,8]
    // d_in[2] = W_noise (unused in eval), d_in[3] = top_k (=2)

    const int N = in_sizes[0] / D;             // 32768 rows

    float* out     = (float*)d_out;
    float* out_w   = out;                      // [N,2]
    float* out_idx = out + (size_t)N * 2;      // [N,2]
    float* out_aux = out + (size_t)N * 4;      // scalar

    prep_kernel<<<16, 128>>>(Wg);
    router_main<<<N / RPB, 128>>>(x, out_w, out_idx, out_aux);
}

// round 7
// speedup vs baseline: 1.5220x; 1.0227x over previous
#include <cuda_runtime.h>
#include <math.h>

// NoisyTopKRouter eval-mode:
//   inputs:  x [4,8192,2048] f32, W_gate [2048,8] f32, W_noise (UNUSED), top_k=2
//   outputs (f32, concatenated in d_out):
//     dispatch_weights [N,2], top_k_idx [N,2] (as float), auxiliary_loss scalar

#define D        2048
#define D4       512        // D / 4
#define NEXP     8
#define RPW      4          // rows per warp
#define WPB      4          // warps per block (128 threads)
#define RPB      (RPW*WPB)  // rows per block = 16
#define NSTG     5          // smem ring slots (4 stages in flight)

__device__ float    g_load[NEXP];
__device__ float    g_imp[NEXP];
__device__ unsigned g_ctr;
// Rearranged W_gate: [(i*4+j)*2 + half][lane] 16B units; half 0 = experts 0..3,
// half 1 = experts 4..7, for column c = i*128 + lane*4 + j.
__device__ float4   g_Wre[16 * 4 * 2 * 32];   // 64 KB

__device__ __forceinline__ unsigned long long pack2(float x, float y) {
    unsigned long long r;
    asm("mov.b64 %0, {%1, %2};" : "=l"(r) : "f"(x), "f"(y));
    return r;
}
__device__ __forceinline__ void unpack2(unsigned long long v, float& x, float& y) {
    asm("mov.b64 {%0, %1}, %2;" : "=f"(x), "=f"(y) : "l"(v));
}
__device__ __forceinline__ void ffma2(unsigned long long& d,
                                      unsigned long long a, unsigned long long b) {
    asm("fma.rn.f32x2 %0, %1, %2, %0;" : "+l"(d) : "l"(a), "l"(b));
}
__device__ __forceinline__ unsigned long long add2(unsigned long long a,
                                                   unsigned long long b) {
    unsigned long long r;
    asm("add.rn.f32x2 %0, %1, %2;" : "=l"(r) : "l"(a), "l"(b));
    return r;
}
__device__ __forceinline__ void cp16(void* smem_dst, const void* gsrc) {
    unsigned s = (unsigned)__cvta_generic_to_shared(smem_dst);
    asm volatile("cp.async.cg.shared.global [%0], [%1], 16;"
                 :: "r"(s), "l"(gsrc) : "memory");
}
#define CP_COMMIT()  asm volatile("cp.async.commit_group;" ::: "memory")
#define CP_WAIT(n)   asm volatile("cp.async.wait_group %0;" :: "n"(n) : "memory")

// Rearrange W_gate into loop-order layout + zero the global accumulators.
__global__ void prep_kernel(const float* __restrict__ Wg) {
    const int c = blockIdx.x * 128 + threadIdx.x;           // column 0..2047
    const float4* Wg4 = (const float4*)Wg;
    float4 f0 = Wg4[c * 2];                                  // experts 0..3
    float4 f1 = Wg4[c * 2 + 1];                              // experts 4..7
    const int i = c >> 7, r = c & 127, lane = r >> 2, j = r & 3;
    const int base = ((i * 4 + j) * 2) * 32 + lane;
    g_Wre[base]      = f0;
    g_Wre[base + 32] = f1;
    if (blockIdx.x == 0) {
        if (threadIdx.x < NEXP) { g_load[threadIdx.x] = 0.f; g_imp[threadIdx.x] = 0.f; }
        if (threadIdx.x == NEXP) g_ctr = 0u;
    }
}

__global__ __launch_bounds__(128, 4)
void router_main(const float* __restrict__ x,
                 float* __restrict__ out_w, float* __restrict__ out_idx,
                 float* __restrict__ out_aux) {
    // Per-warp private x staging ring: [warp][slot][row][lane] 16B units = 40KB.
    __shared__ float4 s_x[WPB][NSTG][RPW][32];
    __shared__ float s_load[NEXP];
    __shared__ float s_imp[NEXP];
    __shared__ unsigned s_ticket;
    const int tid  = threadIdx.x;
    const int warp = tid >> 5;
    const int lane = tid & 31;

    if (tid < NEXP) { s_load[tid] = 0.f; s_imp[tid] = 0.f; }
    __syncthreads();

    const int r0 = (blockIdx.x * WPB + warp) * RPW;          // first row for this warp

    const float4*     x4 = (const float4*)x;
    const ulonglong2* wq = (const ulonglong2*)g_Wre;         // 16B units, dense per warp
    const float4*     gsrc = x4 + (size_t)r0 * D4 + lane;

    unsigned long long acc[RPW][4];
#pragma unroll
    for (int rr = 0; rr < RPW; rr++)
#pragma unroll
        for (int p = 0; p < 4; p++) acc[rr][p] = 0ull;

    // Prologue: issue 4 stages (lane-private 16B copies — no barriers needed).
#pragma unroll
    for (int st = 0; st < 4; st++) {
#pragma unroll
        for (int rr = 0; rr < RPW; rr++)
            cp16(&s_x[warp][st][rr][lane], gsrc + rr * D4 + st * 32);
        CP_COMMIT();
    }

#pragma unroll 1
    for (int i = 0; i < 16; i++) {                           // 16 groups of 128 cols
        CP_WAIT(3);                                          // stage i landed
        __syncwarp();

        const int sl = i % NSTG;
        float4 xv[RPW];
#pragma unroll
        for (int rr = 0; rr < RPW; rr++)
            xv[rr] = s_x[warp][sl][rr][lane];                // LDS.128, lane-private

        // Refill: issue stage i+4 into the slot consumed at iter i-1.
        if (i + 4 < 16) {
            const int st = i + 4, sl2 = st % NSTG;
#pragma unroll
            for (int rr = 0; rr < RPW; rr++)
                cp16(&s_x[warp][sl2][rr][lane], gsrc + rr * D4 + st * 32);
        }
        CP_COMMIT();                                         // commit (possibly empty)

#pragma unroll
        for (int j = 0; j < 4; j++) {
            // Dense, L1-resident weight loads (lane stride = 16B)
            ulonglong2 wa = wq[((i * 4 + j) * 2 + 0) * 32 + lane];  // experts 0..3
            ulonglong2 wb = wq[((i * 4 + j) * 2 + 1) * 32 + lane];  // experts 4..7
#pragma unroll
            for (int rr = 0; rr < RPW; rr++) {
                float xc = (j == 0) ? xv[rr].x : (j == 1) ? xv[rr].y
                         : (j == 2) ? xv[rr].z : xv[rr].w;
                unsigned long long xb = pack2(xc, xc);
                ffma2(acc[rr][0], xb, wa.x);
                ffma2(acc[rr][1], xb, wa.y);
                ffma2(acc[rr][2], xb, wb.x);
                ffma2(acc[rr][3], xb, wb.y);
            }
        }
    }

    // Cross-lane reduction: 64-bit butterfly (once per 4 rows).
#pragma unroll
    for (int rr = 0; rr < RPW; rr++)
#pragma unroll
        for (int p = 0; p < 4; p++) {
#pragma unroll
            for (int off = 16; off > 0; off >>= 1)
                acc[rr][p] = add2(acc[rr][p],
                                  __shfl_xor_sync(0xffffffffu, acc[rr][p], off));
        }

    // Lane rr owns row r0+rr for the epilogue.
    unsigned long long mine[4];
#pragma unroll
    for (int rr = 0; rr < RPW; rr++)
        if (lane == rr) {
            mine[0] = acc[rr][0]; mine[1] = acc[rr][1];
            mine[2] = acc[rr][2]; mine[3] = acc[rr][3];
        }

    if (lane < RPW) {
        float h[NEXP];
        unpack2(mine[0], h[0], h[1]);
        unpack2(mine[1], h[2], h[3]);
        unpack2(mine[2], h[4], h[5]);
        unpack2(mine[3], h[6], h[7]);

        const int row = r0 + lane;

        // top-2 (lowest index wins ties, matching jax.lax.top_k)
        int e0 = 0; float v0 = h[0];
#pragma unroll
        for (int e = 1; e < NEXP; e++)
            if (h[e] > v0) { v0 = h[e]; e0 = e; }
        int e1 = -1; float v1 = -3.4e38f;
#pragma unroll
        for (int e = 0; e < NEXP; e++)
            if (e != e0 && h[e] > v1) { v1 = h[e]; e1 = e; }

        float w0 = 1.f / (1.f + expf(v1 - v0));
        float w1 = 1.f - w0;

        float p[NEXP]; float Z = 0.f;
#pragma unroll
        for (int e = 0; e < NEXP; e++) { p[e] = expf(h[e] - v0); Z += p[e]; }
        float invZ = 1.f / Z;
#pragma unroll
        for (int e = 0; e < NEXP; e++) atomicAdd(&s_imp[e], p[e] * invZ);
        atomicAdd(&s_load[e0], 1.f);
        atomicAdd(&s_load[e1], 1.f);

        out_w[row * 2]       = w0;
        out_w[row * 2 + 1]   = w1;
        out_idx[row * 2]     = (float)e0;
        out_idx[row * 2 + 1] = (float)e1;
    }

    __syncthreads();
    if (tid < NEXP) {
        atomicAdd(&g_load[tid], s_load[tid]);
        atomicAdd(&g_imp[tid],  s_imp[tid]);
        __threadfence();
    }
    __syncthreads();
    if (tid == 0) s_ticket = atomicAdd(&g_ctr, 1u);
    __syncthreads();

    // Last block computes the auxiliary loss.
    if (s_ticket == gridDim.x - 1 && tid == 0) {
        volatile float* vl_ = g_load;
        volatile float* vi_ = g_imp;
        float l[NEXP], im[NEXP];
        float ml = 0.f, mi = 0.f;
#pragma unroll
        for (int e = 0; e < NEXP; e++) {
            l[e] = vl_[e]; im[e] = vi_[e];
            ml += l[e];    mi += im[e];
        }
        ml *= (1.f / NEXP);
        mi *= (1.f / NEXP);
        float vl = 0.f, vi = 0.f;
#pragma unroll
        for (int e = 0; e < NEXP; e++) {
            float dl = l[e]  - ml; vl += dl * dl;
            float di = im[e] - mi; vi += di * di;
        }
        vl *= (1.f / (NEXP - 1));   // ddof = 1
        vi *= (1.f / (NEXP - 1));
        float cv = sqrtf(vl) / (ml + 1e-6f) + sqrtf(vi) / (mi + 1e-6f);
        *out_aux = cv * 0.01f;
    }
}

extern "C" void kernel_launch(void* const* d_in, const int* in_sizes, int n_in,
                              void* d_out, int out_size) {
    const float* x  = (const float*)d_in[0];   // [4,8192,2048]
    const float* Wg = (const float*)d_in[1];   // [2048,8]
    // d_in[2] = W_noise (unused in eval), d_in[3] = top_k (=2)

    const int N = in_sizes[0] / D;             // 32768 rows

    float* out     = (float*)d_out;
    float* out_w   = out;                      // [N,2]
    float* out_idx = out + (size_t)N * 2;      // [N,2]
    float* out_aux = out + (size_t)N * 4;      // scalar

    prep_kernel<<<16, 128>>>(Wg);
    router_main<<<N / RPB, 128>>>(x, out_w, out_idx, out_aux);
}